// round 8
// baseline (speedup 1.0000x reference)
#include <cuda_runtime.h>
#include <cuda_bf16.h>
#include <stdint.h>
#include <math.h>

#define L      128
#define B      64
#define IN_F   512
#define ACT_F  512
#define H      1024
#define G4     4096
#define LSTM_IN 1024

#if defined(__CUDA_ARCH__) && (defined(__CUDA_ARCH_FEAT_SM103_ALL) || defined(__CUDA_ARCH_FEAT_SM100_ALL) || defined(__CUDA_ARCH_SPECIFIC__) || defined(__CUDA_ARCH_FAMILY_SPECIFIC__))
#define HAS_TCGEN05 1
#else
#define HAS_TCGEN05 0
#endif

// ---------------- device scratch ----------------
__device__ float g_gact[(size_t)L * B * G4];
__device__ float g_ginp[B * G4];
__device__ float g_c[B * H];
__device__ __nv_bfloat16 g_Whh_hi[G4 * H];
__device__ __nv_bfloat16 g_Whh_lo[G4 * H];
__device__ __nv_bfloat16 g_h_hi[2][B * H];
__device__ __nv_bfloat16 g_h_lo[2][B * H];
__device__ __nv_bfloat16 g_act_hi[(size_t)L * B * ACT_F];
__device__ __nv_bfloat16 g_act_lo[(size_t)L * B * ACT_F];
__device__ __nv_bfloat16 g_Wact_hi[G4 * ACT_F];
__device__ __nv_bfloat16 g_Wact_lo[G4 * ACT_F];
__device__ float g_part[32 * 3 * 128 * 64];    // K-split partials per j-slice
__device__ unsigned g_pflag[128];              // partial-ready flags
__device__ unsigned g_bar;                     // step barrier (q0 arrivals only)

__device__ __forceinline__ float sigm_fast(float x) {
    return __fdividef(1.0f, 1.0f + __expf(-x));
}
__device__ __forceinline__ float tanh_fast(float x) {
    return 1.0f - __fdividef(2.0f, __expf(2.0f * x) + 1.0f);
}

// ---------------- PTX helpers ----------------
__device__ __forceinline__ uint32_t smem_u32(const void* p) {
    uint32_t a;
    asm("{ .reg .u64 t; cvta.to.shared.u64 t, %1; cvt.u32.u64 %0, t; }" : "=r"(a) : "l"(p));
    return a;
}

#define CP_ASYNC16(dst, src) \
    asm volatile("cp.async.cg.shared.global [%0], [%1], 16;" :: "r"((uint32_t)(dst)), "l"(src) : "memory")
#define CP_COMMIT() asm volatile("cp.async.commit_group;" ::: "memory")
#define CP_WAIT(n)  asm volatile("cp.async.wait_group %0;" :: "n"(n) : "memory")
#define CP_MBAR_ARRIVE(addr) \
    asm volatile("cp.async.mbarrier.arrive.noinc.shared.b64 [%0];" :: "r"((uint32_t)(addr)) : "memory")

#define MBARRIER_INIT(addr, cnt) \
    asm volatile("mbarrier.init.shared.b64 [%0], %1;" :: "r"((uint32_t)(addr)), "r"((uint32_t)(cnt)) : "memory")
#define MBARRIER_INVAL(addr) \
    asm volatile("mbarrier.inval.shared.b64 [%0];" :: "r"((uint32_t)(addr)) : "memory")

#define MBARRIER_WAIT_PARITY(mbar_smem_addr, phase_parity) do { \
    uint32_t _mbar = (uint32_t)(mbar_smem_addr); \
    uint32_t _parity = (uint32_t)(phase_parity); \
    uint32_t _done; \
    asm volatile( \
        "{\n\t" \
        ".reg .pred p;\n\t" \
        "mbarrier.try_wait.parity.acquire.cta.shared::cta.b64 p, [%1], %2;\n\t" \
        "selp.b32 %0, 1, 0, p;\n\t" \
        "}" \
        : "=r"(_done) : "r"(_mbar), "r"(_parity) : "memory"); \
    if (!_done) { \
        asm volatile( \
            "{\n\t" \
            ".reg .pred P1;\n\t" \
            "WAIT_LOOP_%=:\n\t" \
            "mbarrier.try_wait.parity.acquire.cta.shared::cta.b64 P1, [%0], %1, 0x989680;\n\t" \
            "@P1 bra.uni WAIT_DONE_%=;\n\t" \
            "bra.uni WAIT_LOOP_%=;\n\t" \
            "WAIT_DONE_%=:\n\t" \
            "}" \
            :: "r"(_mbar), "r"(_parity) : "memory"); \
    } \
} while(0)

#if HAS_TCGEN05
__device__ __forceinline__ uint32_t elect1() {
    uint32_t p;
    asm volatile("{ .reg .pred p; elect.sync _|p, 0xFFFFFFFF; selp.b32 %0, 1, 0, p; }" : "=r"(p));
    return p;
}

#define TCGEN05_ALLOC(smem_result_addr, nCols) \
    asm volatile("tcgen05.alloc.cta_group::1.sync.aligned.shared::cta.b32 [%0], %1;" \
        :: "r"((uint32_t)(smem_result_addr)), "r"((uint32_t)(nCols)) : "memory")
#define TCGEN05_DEALLOC(tmem_addr, nCols) \
    asm volatile("tcgen05.dealloc.cta_group::1.sync.aligned.b32 %0, %1;" :: "r"(tmem_addr), "r"(nCols))
#define TCGEN05_COMMIT(mbar_smem_addr) \
    asm volatile("tcgen05.commit.cta_group::1.mbarrier::arrive::one.shared::cluster.b64 [%0];" \
        :: "r"((uint32_t)(mbar_smem_addr)) : "memory")
#define TCGEN05_FENCE_AFTER() asm volatile("tcgen05.fence::after_thread_sync;" ::: "memory")
#define TCGEN05_FENCE_BEFORE() asm volatile("tcgen05.fence::before_thread_sync;" ::: "memory")
#define TCGEN05_WAIT_LD() asm volatile("tcgen05.wait::ld.sync.aligned;" ::: "memory")
#define FENCE_PROXY_ASYNC_SHARED_CTA() asm volatile("fence.proxy.async.shared::cta;" ::: "memory")

#define TCGEN05_LD_32X32B_X32(r, tmem_addr) \
    asm volatile( \
        "tcgen05.ld.sync.aligned.32x32b.x32.b32 " \
        "{%0, %1, %2, %3, %4, %5, %6, %7, " \
        " %8, %9, %10, %11, %12, %13, %14, %15, " \
        " %16, %17, %18, %19, %20, %21, %22, %23, " \
        " %24, %25, %26, %27, %28, %29, %30, %31}, [%32];" \
        : "=r"((r)[0]),  "=r"((r)[1]),  "=r"((r)[2]),  "=r"((r)[3]), \
          "=r"((r)[4]),  "=r"((r)[5]),  "=r"((r)[6]),  "=r"((r)[7]), \
          "=r"((r)[8]),  "=r"((r)[9]),  "=r"((r)[10]), "=r"((r)[11]), \
          "=r"((r)[12]), "=r"((r)[13]), "=r"((r)[14]), "=r"((r)[15]), \
          "=r"((r)[16]), "=r"((r)[17]), "=r"((r)[18]), "=r"((r)[19]), \
          "=r"((r)[20]), "=r"((r)[21]), "=r"((r)[22]), "=r"((r)[23]), \
          "=r"((r)[24]), "=r"((r)[25]), "=r"((r)[26]), "=r"((r)[27]), \
          "=r"((r)[28]), "=r"((r)[29]), "=r"((r)[30]), "=r"((r)[31]) \
        : "r"(tmem_addr))

__device__ __forceinline__ void mma_bf16_ss(uint32_t d, uint64_t a, uint64_t b,
                                            uint32_t idesc, uint32_t en) {
    asm volatile(
        "{\n\t"
        ".reg .pred p;\n\t"
        "setp.ne.u32 p, %5, 0;\n\t"
        "tcgen05.mma.cta_group::1.kind::f16 [%0], %1, %2, %3, {%4, %4, %4, %4}, p;\n\t"
        "}"
        :: "r"(d), "l"(a), "l"(b), "r"(idesc), "r"(0u), "r"(en) : "memory");
}

static __device__ __forceinline__ uint64_t make_desc(uint32_t base) {
    const uint64_t BASE =
        (uint64_t(2) << 61) | (uint64_t(1) << 46) | (uint64_t(64) << 32) | (uint64_t(1) << 16);
    return BASE | ((uint64_t)(base >> 4) & 0x3FFF);
}
#endif // HAS_TCGEN05

__device__ __forceinline__ uint32_t swz(uint32_t x) { return x ^ ((x >> 3) & 0x70); }

#define MMA_IDESC_N64  0x8100490u
#define MMA_IDESC_N256 0x8400490u

// ---------------- SMEM layout: persistent decoder (W-resident, K-split-4) ----------------
#define D_TMEM 0
#define D_MMB  8
#define D_LMB  16
#define D_W    1024                   // 8 tiles x 16384 (hi c0..3, lo c0..3)
#define D_H    (1024 + 131072)        // 132096: hhi tiles c0..3 x 8192
#define D_HLO  (D_H + 32768)          // hlo tiles
#define D_G    (D_H + 65536)          // 197632: 128 x 65 fp32 = 33280
#define D_SMEM (D_G + 33280)          // 230912

// ---------------- SMEM layout: gact_tc kernel ----------------
#define GT_STRIDE 98304
#define GT_AHI    0
#define GT_ALO    16384
#define GT_BHI    32768
#define GT_BLO    65536
#define GT_SMEM_TOTAL (1024 + 2 * GT_STRIDE)
#define SM_TMEM 0
#define SM_MB0  8

// ---------------- init ----------------
__global__ void init_state_kernel(const float* __restrict__ h0, const float* __restrict__ c0) {
    int i = blockIdx.x * blockDim.x + threadIdx.x;
    if (i == 0) g_bar = 0;
    if (i < 128) g_pflag[i] = 0;
    if (i < B * H) {
        g_c[i] = c0[i];
        float h = h0[i];
        __nv_bfloat16 hi = __float2bfloat16(h);
        g_h_hi[0][i] = hi;
        g_h_lo[0][i] = __float2bfloat16(h - __bfloat162float(hi));
    }
}

// ---------------- combined split kernel ----------------
#define N_WHH  (G4 * H)
#define N_ACT  (L * B * ACT_F)
#define N_WACT (G4 * ACT_F)
__global__ void split_all_kernel(const float* __restrict__ Whh,
                                 const float* __restrict__ act,
                                 const float* __restrict__ W_ih) {
    int i = blockIdx.x * blockDim.x + threadIdx.x;
    if (i < N_WHH) {
        float w = Whh[i];
        __nv_bfloat16 hi = __float2bfloat16(w);
        g_Whh_hi[i] = hi;
        g_Whh_lo[i] = __float2bfloat16(w - __bfloat162float(hi));
    } else if (i < N_WHH + N_ACT) {
        int j = i - N_WHH;
        float v = act[j];
        __nv_bfloat16 hi = __float2bfloat16(v);
        g_act_hi[j] = hi;
        g_act_lo[j] = __float2bfloat16(v - __bfloat162float(hi));
    } else if (i < N_WHH + N_ACT + N_WACT) {
        int j = i - N_WHH - N_ACT;
        int n = j >> 9, k = j & 511;
        float w = W_ih[(size_t)n * LSTM_IN + IN_F + k];
        __nv_bfloat16 hi = __float2bfloat16(w);
        g_Wact_hi[j] = hi;
        g_Wact_lo[j] = __float2bfloat16(w - __bfloat162float(hi));
    }
}

// ---------------- ginp (fp32) ----------------
__global__ void ginp_kernel(const float* __restrict__ inp,
                            const float* __restrict__ W_ih,
                            const float* __restrict__ b_ih,
                            const float* __restrict__ b_hh) {
    __shared__ float aT[16][68];
    __shared__ float wT[16][132];
    const int nb0 = blockIdx.x * 128;
    const int tid = threadIdx.x;
    const int tx = tid & 31;
    const int ty = tid >> 5;
    float acc[8][4];
    #pragma unroll
    for (int i = 0; i < 8; i++)
        #pragma unroll
        for (int j = 0; j < 4; j++) acc[i][j] = 0.0f;

    const int lb  = tid >> 2;
    const int lq  = (tid & 3) * 4;
    const int lc  = tid >> 1;
    const int lhf = (tid & 1) * 8;

    for (int k0 = 0; k0 < IN_F; k0 += 16) {
        {
            float4 v = *(const float4*)(inp + lb * IN_F + k0 + lq);
            aT[lq + 0][lb] = v.x; aT[lq + 1][lb] = v.y;
            aT[lq + 2][lb] = v.z; aT[lq + 3][lb] = v.w;
        }
        {
            const float* wp = W_ih + (size_t)(nb0 + lc) * LSTM_IN + k0 + lhf;
            float4 v0 = *(const float4*)(wp);
            float4 v1 = *(const float4*)(wp + 4);
            wT[lhf + 0][lc] = v0.x; wT[lhf + 1][lc] = v0.y;
            wT[lhf + 2][lc] = v0.z; wT[lhf + 3][lc] = v0.w;
            wT[lhf + 4][lc] = v1.x; wT[lhf + 5][lc] = v1.y;
            wT[lhf + 6][lc] = v1.z; wT[lhf + 7][lc] = v1.w;
        }
        __syncthreads();
        #pragma unroll
        for (int kk = 0; kk < 16; kk++) {
            float av[8];
            float4 u0 = *(const float4*)&aT[kk][ty * 8];
            float4 u1 = *(const float4*)&aT[kk][ty * 8 + 4];
            av[0] = u0.x; av[1] = u0.y; av[2] = u0.z; av[3] = u0.w;
            av[4] = u1.x; av[5] = u1.y; av[6] = u1.z; av[7] = u1.w;
            float wv[4];
            #pragma unroll
            for (int jj = 0; jj < 4; jj++) wv[jj] = wT[kk][tx + 32 * jj];
            #pragma unroll
            for (int i = 0; i < 8; i++)
                #pragma unroll
                for (int jj = 0; jj < 4; jj++) acc[i][jj] += av[i] * wv[jj];
        }
        __syncthreads();
    }
    #pragma unroll
    for (int jj = 0; jj < 4; jj++) {
        int n = nb0 + tx + 32 * jj;
        float bb = b_ih[n] + b_hh[n];
        #pragma unroll
        for (int i = 0; i < 8; i++) {
            int b = ty * 8 + i;
            g_ginp[b * G4 + n] = acc[i][jj] + bb;
        }
    }
}

// ---------------- gact_tc (unchanged) ----------------
__global__ void __launch_bounds__(256, 1) gact_tc_kernel(const float* __restrict__ act,
                                                         const float* __restrict__ W_ih) {
    extern __shared__ char smem[];
    const int tid = threadIdx.x;
    const int n0 = blockIdx.x * 256;
    const int r0 = blockIdx.y * 128;

#if HAS_TCGEN05
    uint32_t sb = smem_u32(smem);
    const int wid = tid >> 5;
    const int lid = tid & 31;

    if (wid == 0) TCGEN05_ALLOC(sb + SM_TMEM, 256);
    if (tid == 0) { MBARRIER_INIT(sb + SM_MB0, 1); MBARRIER_INIT(sb + SM_MB0 + 8, 1); }
    __syncthreads();
    uint32_t tmem;
    asm volatile("ld.shared.b32 %0, [%1];" : "=r"(tmem) : "r"(sb + SM_TMEM));

    const char* ahi = (const char*)g_act_hi;
    const char* alo = (const char*)g_act_lo;
    const char* whi = (const char*)g_Wact_hi;
    const char* wlo = (const char*)g_Wact_lo;

    for (int kc = 0; kc < 8; kc++) {
        const int buf = kc & 1;
        if (kc >= 2) {
            uint32_t mb = sb + SM_MB0 + 8 * buf;
            MBARRIER_WAIT_PARITY(mb, ((kc >> 1) - 1) & 1);
        }
        uint32_t base = sb + 1024 + buf * GT_STRIDE;
        #pragma unroll
        for (int i = 0; i < 4; i++) {
            int u = tid + i * 256;
            int row = u >> 3, qq = u & 7;
            size_t so = ((size_t)(r0 + row) * 64 + kc * 8 + qq) * 16;
            uint32_t d = base + GT_AHI + swz(row * 128 + qq * 16);
            CP_ASYNC16(d, ahi + so);
            CP_ASYNC16(d + (GT_ALO - GT_AHI), alo + so);
        }
        #pragma unroll
        for (int i = 0; i < 8; i++) {
            int u = tid + i * 256;
            int row = u >> 3, qq = u & 7;
            size_t so = ((size_t)(n0 + row) * 64 + kc * 8 + qq) * 16;
            uint32_t d = base + GT_BHI + swz(row * 128 + qq * 16);
            CP_ASYNC16(d, whi + so);
            CP_ASYNC16(d + (GT_BLO - GT_BHI), wlo + so);
        }
        CP_COMMIT();
        if (kc >= 1) {
            CP_WAIT(1);
            __syncthreads();
            if (wid == 0) {
                FENCE_PROXY_ASYNC_SHARED_CTA();
                if (elect1()) {
                    int j = kc - 1;
                    uint32_t b2 = sb + 1024 + (j & 1) * GT_STRIDE;
                    uint64_t ah = make_desc(b2 + GT_AHI);
                    uint64_t al = make_desc(b2 + GT_ALO);
                    uint64_t bh = make_desc(b2 + GT_BHI);
                    uint64_t bl = make_desc(b2 + GT_BLO);
                    #pragma unroll
                    for (int k = 0; k < 4; k++)
                        mma_bf16_ss(tmem, ah + 2 * k, bh + 2 * k, MMA_IDESC_N256, !(j == 0 && k == 0));
                    #pragma unroll
                    for (int k = 0; k < 4; k++)
                        mma_bf16_ss(tmem, ah + 2 * k, bl + 2 * k, MMA_IDESC_N256, 1);
                    #pragma unroll
                    for (int k = 0; k < 4; k++)
                        mma_bf16_ss(tmem, al + 2 * k, bh + 2 * k, MMA_IDESC_N256, 1);
                    TCGEN05_COMMIT(sb + SM_MB0 + 8 * (j & 1));
                }
            }
        }
    }
    CP_WAIT(0);
    __syncthreads();
    if (wid == 0) {
        FENCE_PROXY_ASYNC_SHARED_CTA();
        if (elect1()) {
            uint32_t b2 = sb + 1024 + GT_STRIDE;
            uint64_t ah = make_desc(b2 + GT_AHI);
            uint64_t al = make_desc(b2 + GT_ALO);
            uint64_t bh = make_desc(b2 + GT_BHI);
            uint64_t bl = make_desc(b2 + GT_BLO);
            #pragma unroll
            for (int k = 0; k < 4; k++)
                mma_bf16_ss(tmem, ah + 2 * k, bh + 2 * k, MMA_IDESC_N256, 1);
            #pragma unroll
            for (int k = 0; k < 4; k++)
                mma_bf16_ss(tmem, ah + 2 * k, bl + 2 * k, MMA_IDESC_N256, 1);
            #pragma unroll
            for (int k = 0; k < 4; k++)
                mma_bf16_ss(tmem, al + 2 * k, bh + 2 * k, MMA_IDESC_N256, 1);
            TCGEN05_COMMIT(sb + SM_MB0 + 8);
        }
    }

    MBARRIER_WAIT_PARITY(sb + SM_MB0, 1);
    MBARRIER_WAIT_PARITY(sb + SM_MB0 + 8, 1);
    TCGEN05_FENCE_AFTER();

    if (wid < 4) {
        int m = wid * 32 + lid;
        int r = r0 + m;
        int b = r & (B - 1);
        const float4* gi4 = (const float4*)g_ginp;
        float* outp = g_gact + (size_t)r * G4 + n0;
        #pragma unroll
        for (int cb = 0; cb < 8; cb++) {
            uint32_t dr[32];
            TCGEN05_LD_32X32B_X32(dr, tmem + cb * 32);
            TCGEN05_WAIT_LD();
            #pragma unroll
            for (int qq = 0; qq < 8; qq++) {
                float4 g = gi4[b * (G4 / 4) + (n0 >> 2) + cb * 8 + qq];
                float4 v;
                v.x = __uint_as_float(dr[qq * 4 + 0]) + g.x;
                v.y = __uint_as_float(dr[qq * 4 + 1]) + g.y;
                v.z = __uint_as_float(dr[qq * 4 + 2]) + g.z;
                v.w = __uint_as_float(dr[qq * 4 + 3]) + g.w;
                *(float4*)(outp + cb * 32 + qq * 4) = v;
            }
        }
        TCGEN05_FENCE_BEFORE();
    }
    __syncthreads();
    if (tid == 0) { MBARRIER_INVAL(sb + SM_MB0); MBARRIER_INVAL(sb + SM_MB0 + 8); }
    if (wid == 0) TCGEN05_DEALLOC(tmem, 256);
#else
    for (int o = 0; o < 128; o++) {
        int r = r0 + o;
        int n = n0 + tid;
        const float* ap = act + (size_t)r * ACT_F;
        const float* wp = W_ih + (size_t)n * LSTM_IN + IN_F;
        float acc = 0.0f;
        for (int k = 0; k < ACT_F; k++) acc += ap[k] * wp[k];
        g_gact[(size_t)r * G4 + n] = acc + g_ginp[(r & (B - 1)) * G4 + n];
    }
#endif
}

// ---------------- persistent decoder: 128 CTAs = 32 j-slices x 4 K-quarters ----------------
__global__ void __launch_bounds__(256, 1) decoder_kernel(const float* __restrict__ Whh,
                                                         float* __restrict__ out) {
    extern __shared__ char smem[];
    uint32_t sb = smem_u32(smem);
    const int tid = threadIdx.x;
    const int wid = tid >> 5;
    const int lid = tid & 31;
    const int jb = blockIdx.x & 31;
    const int q  = blockIdx.x >> 5;
    const int j0 = jb * 32;

#if HAS_TCGEN05
    if (wid == 0) TCGEN05_ALLOC(sb + D_TMEM, 128);
    if (tid == 0) { MBARRIER_INIT(sb + D_MMB, 1); MBARRIER_INIT(sb + D_LMB, 256); }
    __syncthreads();
    uint32_t tmem;
    asm volatile("ld.shared.b32 %0, [%1];" : "=r"(tmem) : "r"(sb + D_TMEM));

    // ---- persistent W load: 8 tiles (hi c0-3, lo c0-3), 128 rows x 64 bf16 each ----
    {
        const char* whi = (const char*)g_Whh_hi;
        const char* wlo = (const char*)g_Whh_lo;
        #pragma unroll
        for (int tile = 0; tile < 8; tile++) {
            const char* src = (tile < 4) ? whi : wlo;
            int c = tile & 3;
            #pragma unroll
            for (int i = 0; i < 4; i++) {
                int u = tid + i * 256;
                int row = u >> 3, qq = u & 7;
                int wrow = ((row >> 5) << 10) + j0 + (row & 31);
                size_t so = ((size_t)wrow * 128 + q * 32 + c * 8 + qq) * 16;
                uint32_t d = sb + D_W + tile * 16384 + swz(row * 128 + qq * 16);
                CP_ASYNC16(d, src + so);
            }
        }
        CP_COMMIT();
        CP_WAIT(0);
    }
    __syncthreads();

    for (int t = 0; t < L; t++) {
        // ---- stream h(t) slice for this quarter: 4 chunks x (hi 8KB + lo 8KB) ----
        {
            const char* hhi = (const char*)g_h_hi[t & 1];
            const char* hlo = (const char*)g_h_lo[t & 1];
            #pragma unroll
            for (int c = 0; c < 4; c++) {
                #pragma unroll
                for (int i = 0; i < 2; i++) {
                    int u = tid + i * 256;
                    int row = u >> 3, qq = u & 7;
                    size_t so = ((size_t)row * 128 + q * 32 + c * 8 + qq) * 16;
                    uint32_t d = sb + D_H + c * 8192 + swz(row * 128 + qq * 16);
                    CP_ASYNC16(d, hhi + so);
                    CP_ASYNC16(d + 32768, hlo + so);
                }
            }
            CP_MBAR_ARRIVE(sb + D_LMB);
        }

        // ---- q0: prefetch gact into regs (overlaps MMA wait) ----
        float ga[32];
        if (q == 0) {
            const float* gp = g_gact + (size_t)t * B * G4;
            #pragma unroll
            for (int k = 0; k < 8; k++) {
                int b = wid * 8 + k;
                #pragma unroll
                for (int g = 0; g < 4; g++)
                    ga[k * 4 + g] = gp[(size_t)b * G4 + g * H + j0 + lid];
            }
        }

        // ---- warp0: wait h, issue 48 MMAs ----
        if (wid == 0) {
            MBARRIER_WAIT_PARITY(sb + D_LMB, t & 1);
            FENCE_PROXY_ASYNC_SHARED_CTA();
            if (elect1()) {
                #pragma unroll
                for (int c = 0; c < 4; c++) {
                    uint64_t ah = make_desc(sb + D_W + c * 16384);
                    uint64_t al = make_desc(sb + D_W + (4 + c) * 16384);
                    uint64_t bh = make_desc(sb + D_H + c * 8192);
                    uint64_t bl = make_desc(sb + D_HLO + c * 8192);
                    #pragma unroll
                    for (int k = 0; k < 4; k++)
                        mma_bf16_ss(tmem, ah + 2 * k, bh + 2 * k, MMA_IDESC_N64, !(c == 0 && k == 0));
                    #pragma unroll
                    for (int k = 0; k < 4; k++)
                        mma_bf16_ss(tmem, ah + 2 * k, bl + 2 * k, MMA_IDESC_N64, 1);
                    #pragma unroll
                    for (int k = 0; k < 4; k++)
                        mma_bf16_ss(tmem, al + 2 * k, bh + 2 * k, MMA_IDESC_N64, 1);
                }
                TCGEN05_COMMIT(sb + D_MMB);
            }
        }

        MBARRIER_WAIT_PARITY(sb + D_MMB, t & 1);
        TCGEN05_FENCE_AFTER();

        // ---- drain D into regs ----
        float sums[32];
        const int row = (wid & 3) * 32 + lid;
        const int cb  = (wid >> 2) * 32;
        {
            uint32_t dr[32];
            TCGEN05_LD_32X32B_X32(dr, tmem + cb);
            TCGEN05_WAIT_LD();
            TCGEN05_FENCE_BEFORE();
            #pragma unroll
            for (int c = 0; c < 32; c++) sums[c] = __uint_as_float(dr[c]);
        }

        if (q != 0) {
            // ---- write partial, release flag ----
            float* dst = g_part + ((size_t)(jb * 3 + (q - 1))) * 8192 + row * 64 + cb;
            #pragma unroll
            for (int c8 = 0; c8 < 8; c8++) {
                float4 v;
                v.x = sums[c8 * 4 + 0]; v.y = sums[c8 * 4 + 1];
                v.z = sums[c8 * 4 + 2]; v.w = sums[c8 * 4 + 3];
                *(float4*)(dst + c8 * 4) = v;
            }
            __threadfence();
            __syncthreads();
            if (tid == 0) {
                asm volatile("st.release.gpu.global.u32 [%0], %1;"
                             :: "l"(&g_pflag[jb * 4 + q]), "r"((unsigned)(t + 1)) : "memory");
            }
        } else {
            // ---- combine partials + epilogue ----
            if (tid == 0) {
                #pragma unroll
                for (int p = 1; p < 4; p++) {
                    unsigned v;
                    do {
                        asm volatile("ld.acquire.gpu.global.u32 %0, [%1];"
                                     : "=r"(v) : "l"(&g_pflag[jb * 4 + p]));
                    } while (v < (unsigned)(t + 1));
                }
            }
            __syncthreads();
            const float* pbase = g_part + (size_t)jb * 3 * 8192 + row * 64 + cb;
            #pragma unroll
            for (int p = 0; p < 3; p++) {
                #pragma unroll
                for (int c8 = 0; c8 < 8; c8++) {
                    float4 v = __ldcg((const float4*)(pbase + p * 8192 + c8 * 4));
                    sums[c8 * 4 + 0] += v.x; sums[c8 * 4 + 1] += v.y;
                    sums[c8 * 4 + 2] += v.z; sums[c8 * 4 + 3] += v.w;
                }
            }
            float* sg = (float*)(smem + D_G);
            #pragma unroll
            for (int c = 0; c < 32; c++) sg[row * 65 + cb + c] = sums[c];
            __syncthreads();

            // ---- LSTM cells ----
            const float* sgc = (const float*)(smem + D_G);
            int b = wid * 8;
            #pragma unroll
            for (int k = 0; k < 8; k++, b++) {
                float s0 = ga[k * 4 + 0] + sgc[( 0 + lid) * 65 + b];
                float s1 = ga[k * 4 + 1] + sgc[(32 + lid) * 65 + b];
                float s2 = ga[k * 4 + 2] + sgc[(64 + lid) * 65 + b];
                float s3 = ga[k * 4 + 3] + sgc[(96 + lid) * 65 + b];
                int gidx = b * H + j0 + lid;
                float c = g_c[gidx];
                float i_ = sigm_fast(s0);
                float f_ = sigm_fast(s1);
                float gg = tanh_fast(s2);
                float o_ = sigm_fast(s3);
                float cn = f_ * c + i_ * gg;
                float hn = o_ * tanh_fast(cn);
                g_c[gidx] = cn;
                out[(size_t)t * B * H + gidx] = hn;
                __nv_bfloat16 hb = __float2bfloat16(hn);
                g_h_hi[(t + 1) & 1][gidx] = hb;
                g_h_lo[(t + 1) & 1][gidx] = __float2bfloat16(hn - __bfloat162float(hb));
            }
            __threadfence();
            __syncthreads();
            if (tid == 0) atomicAdd(&g_bar, 1u);
        }

        // ---- wait h(t+1) ready (32 q0 arrivals) ----
        if (tid == 0) {
            unsigned target = 32u * (unsigned)(t + 1);
            unsigned v;
            do {
                asm volatile("ld.acquire.gpu.global.u32 %0, [%1];" : "=r"(v) : "l"(&g_bar));
            } while (v < target);
        }
        __syncthreads();
    }

    if (tid == 0) { MBARRIER_INVAL(sb + D_MMB); MBARRIER_INVAL(sb + D_LMB); }
    if (wid == 0) TCGEN05_DEALLOC(tmem, 128);
#else
    // ---- SIMT fallback: q0 CTAs compute full K; q>0 idle at barrier ----
    if (q == 0) {
        for (int t = 0; t < L; t++) {
            float* sg = (float*)(smem + D_G);
            float* hs = (float*)(smem + D_W);
            const int r   = tid >> 1;
            const int bb0 = (tid & 1) * 32;
            const int wrow = ((r >> 5) << 10) + j0 + (r & 31);
            const float* wp = Whh + (size_t)wrow * H;
            float acc[32];
            #pragma unroll
            for (int i = 0; i < 32; i++) acc[i] = 0.0f;
            for (int kc = 0; kc < 8; kc++) {
                #pragma unroll
                for (int i = 0; i < 32; i++) {
                    int u = tid + i * 256;
                    int b = u >> 7, k = u & 127;
                    int gi = b * H + kc * 128 + k;
                    hs[b * 132 + k] = __bfloat162float(g_h_hi[t & 1][gi]) + __bfloat162float(g_h_lo[t & 1][gi]);
                }
                __syncthreads();
                for (int k = 0; k < 128; k++) {
                    float w = wp[kc * 128 + k];
                    #pragma unroll
                    for (int i = 0; i < 32; i++)
                        acc[i] += w * hs[(bb0 + i) * 132 + k];
                }
                __syncthreads();
            }
            #pragma unroll
            for (int i = 0; i < 32; i++) sg[r * 65 + bb0 + i] = acc[i];
            __syncthreads();

            const float* sgc = (const float*)(smem + D_G);
            const float* gp = g_gact + (size_t)t * B * G4;
            int b = wid * 8;
            #pragma unroll
            for (int k = 0; k < 8; k++, b++) {
                float s0 = gp[(size_t)b * G4 + 0 * H + j0 + lid] + sgc[( 0 + lid) * 65 + b];
                float s1 = gp[(size_t)b * G4 + 1 * H + j0 + lid] + sgc[(32 + lid) * 65 + b];
                float s2 = gp[(size_t)b * G4 + 2 * H + j0 + lid] + sgc[(64 + lid) * 65 + b];
                float s3 = gp[(size_t)b * G4 + 3 * H + j0 + lid] + sgc[(96 + lid) * 65 + b];
                int gidx = b * H + j0 + lid;
                float c = g_c[gidx];
                float i_ = sigm_fast(s0);
                float f_ = sigm_fast(s1);
                float gg = tanh_fast(s2);
                float o_ = sigm_fast(s3);
                float cn = f_ * c + i_ * gg;
                float hn = o_ * tanh_fast(cn);
                g_c[gidx] = cn;
                out[(size_t)t * B * H + gidx] = hn;
                __nv_bfloat16 hb = __float2bfloat16(hn);
                g_h_hi[(t + 1) & 1][gidx] = hb;
                g_h_lo[(t + 1) & 1][gidx] = __float2bfloat16(hn - __bfloat162float(hb));
            }
            __threadfence();
            __syncthreads();
            if (tid == 0) atomicAdd(&g_bar, 1u);
            if (tid == 0) {
                unsigned target = 32u * (unsigned)(t + 1);
                unsigned v;
                do {
                    asm volatile("ld.acquire.gpu.global.u32 %0, [%1];" : "=r"(v) : "l"(&g_bar));
                } while (v < target);
            }
            __syncthreads();
        }
    } else {
        for (int t = 0; t < L; t++) {
            if (tid == 0) {
                unsigned target = 32u * (unsigned)(t + 1);
                unsigned v;
                do {
                    asm volatile("ld.acquire.gpu.global.u32 %0, [%1];" : "=r"(v) : "l"(&g_bar));
                } while (v < target);
            }
            __syncthreads();
        }
    }
#endif
}

// ---------------- tail ----------------
__global__ void tail_kernel(float* __restrict__ out) {
    int idx = blockIdx.x * blockDim.x + threadIdx.x;
    if (idx >= B * H) return;
    out[(size_t)L * B * H + idx]         = out[(size_t)(L - 1) * B * H + idx];
    out[(size_t)L * B * H + B * H + idx] = g_c[idx];
}

extern "C" void kernel_launch(void* const* d_in, const int* in_sizes, int n_in,
                              void* d_out, int out_size) {
    const float* inp  = (const float*)d_in[0];
    const float* act  = (const float*)d_in[1];
    const float* h0   = (const float*)d_in[2];
    const float* c0   = (const float*)d_in[3];
    const float* W_ih = (const float*)d_in[4];
    const float* W_hh = (const float*)d_in[5];
    const float* b_ih = (const float*)d_in[6];
    const float* b_hh = (const float*)d_in[7];
    float* out = (float*)d_out;
    (void)in_sizes; (void)n_in;

    cudaFuncSetAttribute(decoder_kernel, cudaFuncAttributeMaxDynamicSharedMemorySize, D_SMEM);
    cudaFuncSetAttribute(gact_tc_kernel, cudaFuncAttributeMaxDynamicSharedMemorySize, GT_SMEM_TOTAL);

    init_state_kernel<<<(B * H + 255) / 256, 256>>>(h0, c0);
    split_all_kernel<<<(N_WHH + N_ACT + N_WACT + 255) / 256, 256>>>(W_hh, act, W_ih);
    ginp_kernel<<<32, 256>>>(inp, W_ih, b_ih, b_hh);
    gact_tc_kernel<<<dim3(16, 64), 256, GT_SMEM_TOTAL>>>(act, W_ih);

    decoder_kernel<<<128, 256, D_SMEM>>>(W_hh, out);

    if (out_size >= L * B * H + 2 * B * H) {
        tail_kernel<<<(B * H + 255) / 256, 256>>>(out);
    }
}

// round 13
// speedup vs baseline: 1.1397x; 1.1397x over previous
#include <cuda_runtime.h>
#include <cuda_bf16.h>
#include <stdint.h>
#include <math.h>

#define L      128
#define B      64
#define IN_F   512
#define ACT_F  512
#define H      1024
#define G4     4096
#define LSTM_IN 1024

#if defined(__CUDA_ARCH__) && (defined(__CUDA_ARCH_FEAT_SM103_ALL) || defined(__CUDA_ARCH_FEAT_SM100_ALL) || defined(__CUDA_ARCH_SPECIFIC__) || defined(__CUDA_ARCH_FAMILY_SPECIFIC__))
#define HAS_TCGEN05 1
#else
#define HAS_TCGEN05 0
#endif

// ---------------- device scratch ----------------
__device__ float g_gact[(size_t)L * B * G4];
__device__ float g_ginp[B * G4];
__device__ float g_c[B * H];
__device__ __nv_bfloat16 g_Whh_hi[G4 * H];
__device__ __nv_bfloat16 g_Whh_lo[G4 * H];
__device__ __nv_bfloat16 g_h_hi[2][B * H];
__device__ __nv_bfloat16 g_h_lo[2][B * H];
__device__ __nv_bfloat16 g_act_hi[(size_t)L * B * ACT_F];
__device__ __nv_bfloat16 g_act_lo[(size_t)L * B * ACT_F];
__device__ __nv_bfloat16 g_Wact_hi[G4 * ACT_F];
__device__ __nv_bfloat16 g_Wact_lo[G4 * ACT_F];
__device__ unsigned g_bar;

__device__ __forceinline__ float sigm_fast(float x) {
    return __fdividef(1.0f, 1.0f + __expf(-x));
}
__device__ __forceinline__ float tanh_fast(float x) {
    return 1.0f - __fdividef(2.0f, __expf(2.0f * x) + 1.0f);
}

// ---------------- PTX helpers ----------------
__device__ __forceinline__ uint32_t smem_u32(const void* p) {
    uint32_t a;
    asm("{ .reg .u64 t; cvta.to.shared.u64 t, %1; cvt.u32.u64 %0, t; }" : "=r"(a) : "l"(p));
    return a;
}

#define CP_ASYNC16(dst, src) \
    asm volatile("cp.async.cg.shared.global [%0], [%1], 16;" :: "r"((uint32_t)(dst)), "l"(src) : "memory")
#define CP_COMMIT() asm volatile("cp.async.commit_group;" ::: "memory")
#define CP_WAIT(n)  asm volatile("cp.async.wait_group %0;" :: "n"(n) : "memory")
#define CP_MBAR_ARRIVE(addr) \
    asm volatile("cp.async.mbarrier.arrive.noinc.shared.b64 [%0];" :: "r"((uint32_t)(addr)) : "memory")

#define MBARRIER_INIT(addr, cnt) \
    asm volatile("mbarrier.init.shared.b64 [%0], %1;" :: "r"((uint32_t)(addr)), "r"((uint32_t)(cnt)) : "memory")
#define MBARRIER_INVAL(addr) \
    asm volatile("mbarrier.inval.shared.b64 [%0];" :: "r"((uint32_t)(addr)) : "memory")

#define MBARRIER_WAIT_PARITY(mbar_smem_addr, phase_parity) do { \
    uint32_t _mbar = (uint32_t)(mbar_smem_addr); \
    uint32_t _parity = (uint32_t)(phase_parity); \
    uint32_t _done; \
    asm volatile( \
        "{\n\t" \
        ".reg .pred p;\n\t" \
        "mbarrier.try_wait.parity.acquire.cta.shared::cta.b64 p, [%1], %2;\n\t" \
        "selp.b32 %0, 1, 0, p;\n\t" \
        "}" \
        : "=r"(_done) : "r"(_mbar), "r"(_parity) : "memory"); \
    if (!_done) { \
        asm volatile( \
            "{\n\t" \
            ".reg .pred P1;\n\t" \
            "WAIT_LOOP_%=:\n\t" \
            "mbarrier.try_wait.parity.acquire.cta.shared::cta.b64 P1, [%0], %1, 0x989680;\n\t" \
            "@P1 bra.uni WAIT_DONE_%=;\n\t" \
            "bra.uni WAIT_LOOP_%=;\n\t" \
            "WAIT_DONE_%=:\n\t" \
            "}" \
            :: "r"(_mbar), "r"(_parity) : "memory"); \
    } \
} while(0)

#if HAS_TCGEN05
__device__ __forceinline__ uint32_t elect1() {
    uint32_t p;
    asm volatile("{ .reg .pred p; elect.sync _|p, 0xFFFFFFFF; selp.b32 %0, 1, 0, p; }" : "=r"(p));
    return p;
}

#define TCGEN05_ALLOC(smem_result_addr, nCols) \
    asm volatile("tcgen05.alloc.cta_group::1.sync.aligned.shared::cta.b32 [%0], %1;" \
        :: "r"((uint32_t)(smem_result_addr)), "r"((uint32_t)(nCols)) : "memory")
#define TCGEN05_DEALLOC(tmem_addr, nCols) \
    asm volatile("tcgen05.dealloc.cta_group::1.sync.aligned.b32 %0, %1;" :: "r"(tmem_addr), "r"(nCols))
#define TCGEN05_COMMIT(mbar_smem_addr) \
    asm volatile("tcgen05.commit.cta_group::1.mbarrier::arrive::one.shared::cluster.b64 [%0];" \
        :: "r"((uint32_t)(mbar_smem_addr)) : "memory")
#define TCGEN05_FENCE_AFTER() asm volatile("tcgen05.fence::after_thread_sync;" ::: "memory")
#define TCGEN05_FENCE_BEFORE() asm volatile("tcgen05.fence::before_thread_sync;" ::: "memory")
#define TCGEN05_WAIT_LD() asm volatile("tcgen05.wait::ld.sync.aligned;" ::: "memory")
#define FENCE_PROXY_ASYNC_SHARED_CTA() asm volatile("fence.proxy.async.shared::cta;" ::: "memory")

#define TCGEN05_LD_32X32B_X32(r, tmem_addr) \
    asm volatile( \
        "tcgen05.ld.sync.aligned.32x32b.x32.b32 " \
        "{%0, %1, %2, %3, %4, %5, %6, %7, " \
        " %8, %9, %10, %11, %12, %13, %14, %15, " \
        " %16, %17, %18, %19, %20, %21, %22, %23, " \
        " %24, %25, %26, %27, %28, %29, %30, %31}, [%32];" \
        : "=r"((r)[0]),  "=r"((r)[1]),  "=r"((r)[2]),  "=r"((r)[3]), \
          "=r"((r)[4]),  "=r"((r)[5]),  "=r"((r)[6]),  "=r"((r)[7]), \
          "=r"((r)[8]),  "=r"((r)[9]),  "=r"((r)[10]), "=r"((r)[11]), \
          "=r"((r)[12]), "=r"((r)[13]), "=r"((r)[14]), "=r"((r)[15]), \
          "=r"((r)[16]), "=r"((r)[17]), "=r"((r)[18]), "=r"((r)[19]), \
          "=r"((r)[20]), "=r"((r)[21]), "=r"((r)[22]), "=r"((r)[23]), \
          "=r"((r)[24]), "=r"((r)[25]), "=r"((r)[26]), "=r"((r)[27]), \
          "=r"((r)[28]), "=r"((r)[29]), "=r"((r)[30]), "=r"((r)[31]) \
        : "r"(tmem_addr))

__device__ __forceinline__ void mma_bf16_ss(uint32_t d, uint64_t a, uint64_t b,
                                            uint32_t idesc, uint32_t en) {
    asm volatile(
        "{\n\t"
        ".reg .pred p;\n\t"
        "setp.ne.u32 p, %5, 0;\n\t"
        "tcgen05.mma.cta_group::1.kind::f16 [%0], %1, %2, %3, {%4, %4, %4, %4}, p;\n\t"
        "}"
        :: "r"(d), "l"(a), "l"(b), "r"(idesc), "r"(0u), "r"(en) : "memory");
}

static __device__ __forceinline__ uint64_t make_desc(uint32_t base) {
    const uint64_t BASE =
        (uint64_t(2) << 61) | (uint64_t(1) << 46) | (uint64_t(64) << 32) | (uint64_t(1) << 16);
    return BASE | ((uint64_t)(base >> 4) & 0x3FFF);
}
#endif // HAS_TCGEN05

__device__ __forceinline__ uint32_t swz(uint32_t x) { return x ^ ((x >> 3) & 0x70); }

#define MMA_IDESC_N64  0x8100490u
#define MMA_IDESC_N256 0x8400490u

// ---------------- SMEM layout: persistent decoder (4-stage ring, G aliases buf3) ----------------
#define SM_TMEM   0
#define SM_MMB    8          // mma mbars: 8,16,24,32
#define SM_LMB    40         // ld mbars:  40,48,56,64
#define SM_BUF    1024
#define BUF_STRIDE 49152
#define OFF_AHI   0
#define OFF_ALO   16384
#define OFF_BHI   32768
#define OFF_BLO   40960
#define SM_G      (SM_BUF + 3 * BUF_STRIDE)      // 148480, aliases buf3 (safe: see step ordering)
#define SMEM_TOTAL (SM_BUF + 4 * BUF_STRIDE)     // 197632

// ---------------- SMEM layout: gact_tc kernel ----------------
#define GT_STRIDE 98304
#define GT_AHI    0
#define GT_ALO    16384
#define GT_BHI    32768
#define GT_BLO    65536
#define GT_SMEM_TOTAL (1024 + 2 * GT_STRIDE)
#define GMB0 8

// ---------------- init ----------------
__global__ void init_state_kernel(const float* __restrict__ h0, const float* __restrict__ c0) {
    int i = blockIdx.x * blockDim.x + threadIdx.x;
    if (i == 0) g_bar = 0;
    if (i < B * H) {
        g_c[i] = c0[i];
        float h = h0[i];
        __nv_bfloat16 hi = __float2bfloat16(h);
        g_h_hi[0][i] = hi;
        g_h_lo[0][i] = __float2bfloat16(h - __bfloat162float(hi));
    }
}

// ---------------- combined split kernel ----------------
#define N_WHH  (G4 * H)
#define N_ACT  (L * B * ACT_F)
#define N_WACT (G4 * ACT_F)
__global__ void split_all_kernel(const float* __restrict__ Whh,
                                 const float* __restrict__ act,
                                 const float* __restrict__ W_ih) {
    int i = blockIdx.x * blockDim.x + threadIdx.x;
    if (i < N_WHH) {
        float w = Whh[i];
        __nv_bfloat16 hi = __float2bfloat16(w);
        g_Whh_hi[i] = hi;
        g_Whh_lo[i] = __float2bfloat16(w - __bfloat162float(hi));
    } else if (i < N_WHH + N_ACT) {
        int j = i - N_WHH;
        float v = act[j];
        __nv_bfloat16 hi = __float2bfloat16(v);
        g_act_hi[j] = hi;
        g_act_lo[j] = __float2bfloat16(v - __bfloat162float(hi));
    } else if (i < N_WHH + N_ACT + N_WACT) {
        int j = i - N_WHH - N_ACT;
        int n = j >> 9, k = j & 511;
        float w = W_ih[(size_t)n * LSTM_IN + IN_F + k];
        __nv_bfloat16 hi = __float2bfloat16(w);
        g_Wact_hi[j] = hi;
        g_Wact_lo[j] = __float2bfloat16(w - __bfloat162float(hi));
    }
}

// ---------------- ginp (fp32) ----------------
__global__ void ginp_kernel(const float* __restrict__ inp,
                            const float* __restrict__ W_ih,
                            const float* __restrict__ b_ih,
                            const float* __restrict__ b_hh) {
    __shared__ float aT[16][68];
    __shared__ float wT[16][132];
    const int nb0 = blockIdx.x * 128;
    const int tid = threadIdx.x;
    const int tx = tid & 31;
    const int ty = tid >> 5;
    float acc[8][4];
    #pragma unroll
    for (int i = 0; i < 8; i++)
        #pragma unroll
        for (int j = 0; j < 4; j++) acc[i][j] = 0.0f;

    const int lb  = tid >> 2;
    const int lq  = (tid & 3) * 4;
    const int lc  = tid >> 1;
    const int lhf = (tid & 1) * 8;

    for (int k0 = 0; k0 < IN_F; k0 += 16) {
        {
            float4 v = *(const float4*)(inp + lb * IN_F + k0 + lq);
            aT[lq + 0][lb] = v.x; aT[lq + 1][lb] = v.y;
            aT[lq + 2][lb] = v.z; aT[lq + 3][lb] = v.w;
        }
        {
            const float* wp = W_ih + (size_t)(nb0 + lc) * LSTM_IN + k0 + lhf;
            float4 v0 = *(const float4*)(wp);
            float4 v1 = *(const float4*)(wp + 4);
            wT[lhf + 0][lc] = v0.x; wT[lhf + 1][lc] = v0.y;
            wT[lhf + 2][lc] = v0.z; wT[lhf + 3][lc] = v0.w;
            wT[lhf + 4][lc] = v1.x; wT[lhf + 5][lc] = v1.y;
            wT[lhf + 6][lc] = v1.z; wT[lhf + 7][lc] = v1.w;
        }
        __syncthreads();
        #pragma unroll
        for (int kk = 0; kk < 16; kk++) {
            float av[8];
            float4 u0 = *(const float4*)&aT[kk][ty * 8];
            float4 u1 = *(const float4*)&aT[kk][ty * 8 + 4];
            av[0] = u0.x; av[1] = u0.y; av[2] = u0.z; av[3] = u0.w;
            av[4] = u1.x; av[5] = u1.y; av[6] = u1.z; av[7] = u1.w;
            float wv[4];
            #pragma unroll
            for (int jj = 0; jj < 4; jj++) wv[jj] = wT[kk][tx + 32 * jj];
            #pragma unroll
            for (int i = 0; i < 8; i++)
                #pragma unroll
                for (int jj = 0; jj < 4; jj++) acc[i][jj] += av[i] * wv[jj];
        }
        __syncthreads();
    }
    #pragma unroll
    for (int jj = 0; jj < 4; jj++) {
        int n = nb0 + tx + 32 * jj;
        float bb = b_ih[n] + b_hh[n];
        #pragma unroll
        for (int i = 0; i < 8; i++) {
            int b = ty * 8 + i;
            g_ginp[b * G4 + n] = acc[i][jj] + bb;
        }
    }
}

// ---------------- gact_tc ----------------
__global__ void __launch_bounds__(256, 1) gact_tc_kernel(const float* __restrict__ act,
                                                         const float* __restrict__ W_ih) {
    extern __shared__ char smem[];
    const int tid = threadIdx.x;
    const int n0 = blockIdx.x * 256;
    const int r0 = blockIdx.y * 128;

#if HAS_TCGEN05
    uint32_t sb = smem_u32(smem);
    const int wid = tid >> 5;
    const int lid = tid & 31;

    if (wid == 0) TCGEN05_ALLOC(sb + SM_TMEM, 256);
    if (tid == 0) { MBARRIER_INIT(sb + GMB0, 1); MBARRIER_INIT(sb + GMB0 + 8, 1); }
    __syncthreads();
    uint32_t tmem;
    asm volatile("ld.shared.b32 %0, [%1];" : "=r"(tmem) : "r"(sb + SM_TMEM));

    const char* ahi = (const char*)g_act_hi;
    const char* alo = (const char*)g_act_lo;
    const char* whi = (const char*)g_Wact_hi;
    const char* wlo = (const char*)g_Wact_lo;

    for (int kc = 0; kc < 8; kc++) {
        const int buf = kc & 1;
        if (kc >= 2) {
            uint32_t mb = sb + GMB0 + 8 * buf;
            MBARRIER_WAIT_PARITY(mb, ((kc >> 1) - 1) & 1);
        }
        uint32_t base = sb + 1024 + buf * GT_STRIDE;
        #pragma unroll
        for (int i = 0; i < 4; i++) {
            int u = tid + i * 256;
            int row = u >> 3, qq = u & 7;
            size_t so = ((size_t)(r0 + row) * 64 + kc * 8 + qq) * 16;
            uint32_t d = base + GT_AHI + swz(row * 128 + qq * 16);
            CP_ASYNC16(d, ahi + so);
            CP_ASYNC16(d + (GT_ALO - GT_AHI), alo + so);
        }
        #pragma unroll
        for (int i = 0; i < 8; i++) {
            int u = tid + i * 256;
            int row = u >> 3, qq = u & 7;
            size_t so = ((size_t)(n0 + row) * 64 + kc * 8 + qq) * 16;
            uint32_t d = base + GT_BHI + swz(row * 128 + qq * 16);
            CP_ASYNC16(d, whi + so);
            CP_ASYNC16(d + (GT_BLO - GT_BHI), wlo + so);
        }
        CP_COMMIT();
        if (kc >= 1) {
            CP_WAIT(1);
            __syncthreads();
            if (wid == 0) {
                FENCE_PROXY_ASYNC_SHARED_CTA();
                if (elect1()) {
                    int j = kc - 1;
                    uint32_t b2 = sb + 1024 + (j & 1) * GT_STRIDE;
                    uint64_t ah = make_desc(b2 + GT_AHI);
                    uint64_t al = make_desc(b2 + GT_ALO);
                    uint64_t bh = make_desc(b2 + GT_BHI);
                    uint64_t bl = make_desc(b2 + GT_BLO);
                    #pragma unroll
                    for (int k = 0; k < 4; k++)
                        mma_bf16_ss(tmem, ah + 2 * k, bh + 2 * k, MMA_IDESC_N256, !(j == 0 && k == 0));
                    #pragma unroll
                    for (int k = 0; k < 4; k++)
                        mma_bf16_ss(tmem, ah + 2 * k, bl + 2 * k, MMA_IDESC_N256, 1);
                    #pragma unroll
                    for (int k = 0; k < 4; k++)
                        mma_bf16_ss(tmem, al + 2 * k, bh + 2 * k, MMA_IDESC_N256, 1);
                    TCGEN05_COMMIT(sb + GMB0 + 8 * (j & 1));
                }
            }
        }
    }
    CP_WAIT(0);
    __syncthreads();
    if (wid == 0) {
        FENCE_PROXY_ASYNC_SHARED_CTA();
        if (elect1()) {
            uint32_t b2 = sb + 1024 + GT_STRIDE;
            uint64_t ah = make_desc(b2 + GT_AHI);
            uint64_t al = make_desc(b2 + GT_ALO);
            uint64_t bh = make_desc(b2 + GT_BHI);
            uint64_t bl = make_desc(b2 + GT_BLO);
            #pragma unroll
            for (int k = 0; k < 4; k++)
                mma_bf16_ss(tmem, ah + 2 * k, bh + 2 * k, MMA_IDESC_N256, 1);
            #pragma unroll
            for (int k = 0; k < 4; k++)
                mma_bf16_ss(tmem, ah + 2 * k, bl + 2 * k, MMA_IDESC_N256, 1);
            #pragma unroll
            for (int k = 0; k < 4; k++)
                mma_bf16_ss(tmem, al + 2 * k, bh + 2 * k, MMA_IDESC_N256, 1);
            TCGEN05_COMMIT(sb + GMB0 + 8);
        }
    }

    MBARRIER_WAIT_PARITY(sb + GMB0, 1);
    MBARRIER_WAIT_PARITY(sb + GMB0 + 8, 1);
    TCGEN05_FENCE_AFTER();

    if (wid < 4) {
        int m = wid * 32 + lid;
        int r = r0 + m;
        int b = r & (B - 1);
        const float4* gi4 = (const float4*)g_ginp;
        float* outp = g_gact + (size_t)r * G4 + n0;
        #pragma unroll
        for (int cb = 0; cb < 8; cb++) {
            uint32_t dr[32];
            TCGEN05_LD_32X32B_X32(dr, tmem + cb * 32);
            TCGEN05_WAIT_LD();
            #pragma unroll
            for (int qq = 0; qq < 8; qq++) {
                float4 g = gi4[b * (G4 / 4) + (n0 >> 2) + cb * 8 + qq];
                float4 v;
                v.x = __uint_as_float(dr[qq * 4 + 0]) + g.x;
                v.y = __uint_as_float(dr[qq * 4 + 1]) + g.y;
                v.z = __uint_as_float(dr[qq * 4 + 2]) + g.z;
                v.w = __uint_as_float(dr[qq * 4 + 3]) + g.w;
                *(float4*)(outp + cb * 32 + qq * 4) = v;
            }
        }
        TCGEN05_FENCE_BEFORE();
    }
    __syncthreads();
    if (tid == 0) { MBARRIER_INVAL(sb + GMB0); MBARRIER_INVAL(sb + GMB0 + 8); }
    if (wid == 0) TCGEN05_DEALLOC(tmem, 256);
#else
    for (int o = 0; o < 128; o++) {
        int r = r0 + o;
        int n = n0 + tid;
        const float* ap = act + (size_t)r * ACT_F;
        const float* wp = W_ih + (size_t)n * LSTM_IN + IN_F;
        float acc = 0.0f;
        for (int k = 0; k < ACT_F; k++) acc += ap[k] * wp[k];
        g_gact[(size_t)r * G4 + n] = acc + g_ginp[(r & (B - 1)) * G4 + n];
    }
#endif
}

#if HAS_TCGEN05
// ---------------- decoder helpers ----------------
__device__ __forceinline__ void issue_W(uint32_t base, int n, int tid, int j0,
                                        const char* whi, const char* wlo) {
    #pragma unroll
    for (int i = 0; i < 4; i++) {
        int u = tid + i * 256;
        int row = u >> 3, q = u & 7;
        int wrow = ((row >> 5) << 10) + j0 + (row & 31);
        size_t so = ((size_t)wrow * 128 + n * 8 + q) * 16;
        uint32_t d = base + OFF_AHI + swz(row * 128 + q * 16);
        CP_ASYNC16(d, whi + so);
        CP_ASYNC16(d + (OFF_ALO - OFF_AHI), wlo + so);
    }
}
__device__ __forceinline__ void issue_h(uint32_t base, int n, int tid,
                                        const char* hhi, const char* hlo) {
    #pragma unroll
    for (int i = 0; i < 2; i++) {
        int u = tid + i * 256;
        int row = u >> 3, q = u & 7;
        size_t so = ((size_t)row * 128 + n * 8 + q) * 16;
        uint32_t d = base + OFF_BHI + swz(row * 128 + q * 16);
        CP_ASYNC16(d, hhi + so);
        CP_ASYNC16(d + (OFF_BLO - OFF_BHI), hlo + so);
    }
}
__device__ __forceinline__ void issue_mma(uint32_t tmem, uint32_t base, uint32_t mbar, int first) {
    uint64_t ah = make_desc(base + OFF_AHI);
    uint64_t al = make_desc(base + OFF_ALO);
    uint64_t bh = make_desc(base + OFF_BHI);
    uint64_t bl = make_desc(base + OFF_BLO);
    #pragma unroll
    for (int k = 0; k < 4; k++)
        mma_bf16_ss(tmem, ah + 2 * k, bh + 2 * k, MMA_IDESC_N64, !(first && k == 0));
    #pragma unroll
    for (int k = 0; k < 4; k++)
        mma_bf16_ss(tmem, ah + 2 * k, bl + 2 * k, MMA_IDESC_N64, 1);
    #pragma unroll
    for (int k = 0; k < 4; k++)
        mma_bf16_ss(tmem, al + 2 * k, bh + 2 * k, MMA_IDESC_N64, 1);
    TCGEN05_COMMIT(mbar);
}
#endif

// ---------------- persistent decoder: 32 CTAs, 4-stage ring ----------------
__global__ void __launch_bounds__(256, 1) decoder_kernel(const float* __restrict__ Whh,
                                                         float* __restrict__ out) {
    extern __shared__ char smem[];
    uint32_t sb = smem_u32(smem);
    const int tid = threadIdx.x;
    const int wid = tid >> 5;
    const int lid = tid & 31;
    const int j0 = blockIdx.x * 32;

#if HAS_TCGEN05
    if (wid == 0) TCGEN05_ALLOC(sb + SM_TMEM, 128);
    if (tid == 0) {
        #pragma unroll
        for (int b = 0; b < 4; b++) {
            MBARRIER_INIT(sb + SM_MMB + 8 * b, 1);
            MBARRIER_INIT(sb + SM_LMB + 8 * b, 256);
        }
    }
    __syncthreads();
    uint32_t tmem;
    asm volatile("ld.shared.b32 %0, [%1];" : "=r"(tmem) : "r"(sb + SM_TMEM));

    const char* whi = (const char*)g_Whh_hi;
    const char* wlo = (const char*)g_Whh_lo;
    uint32_t mc[4] = {0, 0, 0, 0};     // mma-mbar phase counters (all threads)
    uint32_t lc[4] = {0, 0, 0, 0};     // ld-mbar phase counters (warp 0)

    // prologue step 0: W for chunks 0,1
    issue_W(sb + SM_BUF, 0, tid, j0, whi, wlo);
    issue_W(sb + SM_BUF + BUF_STRIDE, 1, tid, j0, whi, wlo);
#endif

    for (int t = 0; t < L; t++) {
#if HAS_TCGEN05
        const char* hhi = (const char*)g_h_hi[t & 1];
        const char* hlo = (const char*)g_h_lo[t & 1];

        // h for chunks 0,1 (arrive covers prefetched W too)
        issue_h(sb + SM_BUF, 0, tid, hhi, hlo);
        CP_MBAR_ARRIVE(sb + SM_LMB);
        issue_h(sb + SM_BUF + BUF_STRIDE, 1, tid, hhi, hlo);
        CP_MBAR_ARRIVE(sb + SM_LMB + 8);

        // gact slice into registers (overlaps chunk chain)
        float ga[32];
        {
            const float* gp = g_gact + (size_t)t * B * G4;
            #pragma unroll
            for (int k = 0; k < 8; k++) {
                int b = wid * 8 + k;
                #pragma unroll
                for (int g = 0; g < 4; g++)
                    ga[k * 4 + g] = __ldg(gp + (size_t)b * G4 + g * H + j0 + lid);
            }
        }

        #pragma unroll
        for (int kc = 0; kc < 16; kc++) {
            const int n = kc + 2;
            if (n <= 15) {
                const int b = n & 3;
                if (n >= 4) {
                    // buffer b last used by chunk n-4; wait its MMA completion
                    MBARRIER_WAIT_PARITY(sb + SM_MMB + 8 * b, mc[b] & 1);
                    mc[b]++;
                }
                uint32_t base = sb + SM_BUF + b * BUF_STRIDE;
                issue_W(base, n, tid, j0, whi, wlo);
                issue_h(base, n, tid, hhi, hlo);
                CP_MBAR_ARRIVE(sb + SM_LMB + 8 * b);
            }
            if (wid == 0) {
                const int bb = kc & 3;
                MBARRIER_WAIT_PARITY(sb + SM_LMB + 8 * bb, lc[bb] & 1);
                lc[bb]++;
                FENCE_PROXY_ASYNC_SHARED_CTA();
                if (elect1())
                    issue_mma(tmem, sb + SM_BUF + bb * BUF_STRIDE, sb + SM_MMB + 8 * bb, kc == 0);
            }
        }

        // final completions: chunks 12..15 → buffers 0..3
        #pragma unroll
        for (int b = 0; b < 4; b++) {
            MBARRIER_WAIT_PARITY(sb + SM_MMB + 8 * b, mc[b] & 1);
            mc[b]++;
        }
        TCGEN05_FENCE_AFTER();

        // prologue W for next step (buffers 0,1 free; overlaps drain/epilogue/barrier)
        if (t < L - 1) {
            issue_W(sb + SM_BUF, 0, tid, j0, whi, wlo);
            issue_W(sb + SM_BUF + BUF_STRIDE, 1, tid, j0, whi, wlo);
        }

        // TMEM drain into G (aliases buf3, free now; next write to buf3 is chunk 3 next step)
        {
            int sp = wid & 3;
            int cb = (wid >> 2) * 32;
            uint32_t dr[32];
            TCGEN05_LD_32X32B_X32(dr, tmem + cb);
            TCGEN05_WAIT_LD();
            TCGEN05_FENCE_BEFORE();
            int r = sp * 32 + lid;
            float* sg = (float*)(smem + SM_G) + r * 65 + cb;
            #pragma unroll
            for (int c = 0; c < 32; c++) sg[c] = __uint_as_float(dr[c]);
        }
        __syncthreads();

        // ---- LSTM cells ----
        {
            const float* sgc = (const float*)(smem + SM_G);
            int b = wid * 8;
            #pragma unroll
            for (int k = 0; k < 8; k++, b++) {
                float s0 = ga[k * 4 + 0] + sgc[( 0 + lid) * 65 + b];
                float s1 = ga[k * 4 + 1] + sgc[(32 + lid) * 65 + b];
                float s2 = ga[k * 4 + 2] + sgc[(64 + lid) * 65 + b];
                float s3 = ga[k * 4 + 3] + sgc[(96 + lid) * 65 + b];
                int gidx = b * H + j0 + lid;
                float c = g_c[gidx];
                float i_ = sigm_fast(s0);
                float f_ = sigm_fast(s1);
                float gg = tanh_fast(s2);
                float o_ = sigm_fast(s3);
                float cn = f_ * c + i_ * gg;
                float hn = o_ * tanh_fast(cn);
                g_c[gidx] = cn;
                out[(size_t)t * B * H + gidx] = hn;
                __nv_bfloat16 hb = __float2bfloat16(hn);
                g_h_hi[(t + 1) & 1][gidx] = hb;
                g_h_lo[(t + 1) & 1][gidx] = __float2bfloat16(hn - __bfloat162float(hb));
            }
        }

        // ---- global step barrier ----
        __threadfence();
        __syncthreads();
        if (tid == 0) {
            atomicAdd(&g_bar, 1u);
            unsigned target = 32u * (unsigned)(t + 1);
            unsigned v;
            do {
                asm volatile("ld.acquire.gpu.global.u32 %0, [%1];" : "=r"(v) : "l"(&g_bar));
            } while (v < target);
        }
        __syncthreads();
#else
        // ---- SIMT fp32 fallback ----
        {
            float* sg = (float*)(smem + SM_G);
            float* hs = (float*)(smem + SM_BUF);
            const int r   = tid >> 1;
            const int bb0 = (tid & 1) * 32;
            const int wrow = ((r >> 5) << 10) + j0 + (r & 31);
            const float* wp = Whh + (size_t)wrow * H;
            float acc[32];
            #pragma unroll
            for (int i = 0; i < 32; i++) acc[i] = 0.0f;
            for (int kc = 0; kc < 8; kc++) {
                #pragma unroll
                for (int i = 0; i < 32; i++) {
                    int u = tid + i * 256;
                    int b = u >> 7, k = u & 127;
                    int gi = b * H + kc * 128 + k;
                    hs[b * 132 + k] = __bfloat162float(g_h_hi[t & 1][gi]) + __bfloat162float(g_h_lo[t & 1][gi]);
                }
                __syncthreads();
                for (int k = 0; k < 128; k++) {
                    float w = wp[kc * 128 + k];
                    #pragma unroll
                    for (int i = 0; i < 32; i++)
                        acc[i] += w * hs[(bb0 + i) * 132 + k];
                }
                __syncthreads();
            }
            #pragma unroll
            for (int i = 0; i < 32; i++) sg[r * 65 + bb0 + i] = acc[i];
        }
        __syncthreads();
        {
            const float* sgc = (const float*)(smem + SM_G);
            const float* gp = g_gact + (size_t)t * B * G4;
            int b = wid * 8;
            #pragma unroll
            for (int k = 0; k < 8; k++, b++) {
                float s0 = gp[(size_t)b * G4 + 0 * H + j0 + lid] + sgc[( 0 + lid) * 65 + b];
                float s1 = gp[(size_t)b * G4 + 1 * H + j0 + lid] + sgc[(32 + lid) * 65 + b];
                float s2 = gp[(size_t)b * G4 + 2 * H + j0 + lid] + sgc[(64 + lid) * 65 + b];
                float s3 = gp[(size_t)b * G4 + 3 * H + j0 + lid] + sgc[(96 + lid) * 65 + b];
                int gidx = b * H + j0 + lid;
                float c = g_c[gidx];
                float i_ = sigm_fast(s0);
                float f_ = sigm_fast(s1);
                float gg = tanh_fast(s2);
                float o_ = sigm_fast(s3);
                float cn = f_ * c + i_ * gg;
                float hn = o_ * tanh_fast(cn);
                g_c[gidx] = cn;
                out[(size_t)t * B * H + gidx] = hn;
                __nv_bfloat16 hb = __float2bfloat16(hn);
                g_h_hi[(t + 1) & 1][gidx] = hb;
                g_h_lo[(t + 1) & 1][gidx] = __float2bfloat16(hn - __bfloat162float(hb));
            }
        }
        __threadfence();
        __syncthreads();
        if (tid == 0) {
            atomicAdd(&g_bar, 1u);
            unsigned target = 32u * (unsigned)(t + 1);
            unsigned v;
            do {
                asm volatile("ld.acquire.gpu.global.u32 %0, [%1];" : "=r"(v) : "l"(&g_bar));
            } while (v < target);
        }
        __syncthreads();
#endif
    }

#if HAS_TCGEN05
    if (tid == 0) {
        #pragma unroll
        for (int b = 0; b < 4; b++) {
            MBARRIER_INVAL(sb + SM_MMB + 8 * b);
            MBARRIER_INVAL(sb + SM_LMB + 8 * b);
        }
    }
    if (wid == 0) TCGEN05_DEALLOC(tmem, 128);
#endif
}

// ---------------- tail ----------------
__global__ void tail_kernel(float* __restrict__ out) {
    int idx = blockIdx.x * blockDim.x + threadIdx.x;
    if (idx >= B * H) return;
    out[(size_t)L * B * H + idx]         = out[(size_t)(L - 1) * B * H + idx];
    out[(size_t)L * B * H + B * H + idx] = g_c[idx];
}

extern "C" void kernel_launch(void* const* d_in, const int* in_sizes, int n_in,
                              void* d_out, int out_size) {
    const float* inp  = (const float*)d_in[0];
    const float* act  = (const float*)d_in[1];
    const float* h0   = (const float*)d_in[2];
    const float* c0   = (const float*)d_in[3];
    const float* W_ih = (const float*)d_in[4];
    const float* W_hh = (const float*)d_in[5];
    const float* b_ih = (const float*)d_in[6];
    const float* b_hh = (const float*)d_in[7];
    float* out = (float*)d_out;
    (void)in_sizes; (void)n_in;

    cudaFuncSetAttribute(decoder_kernel, cudaFuncAttributeMaxDynamicSharedMemorySize, SMEM_TOTAL);
    cudaFuncSetAttribute(gact_tc_kernel, cudaFuncAttributeMaxDynamicSharedMemorySize, GT_SMEM_TOTAL);

    init_state_kernel<<<(B * H + 255) / 256, 256>>>(h0, c0);
    split_all_kernel<<<(N_WHH + N_ACT + N_WACT + 255) / 256, 256>>>(W_hh, act, W_ih);
    ginp_kernel<<<32, 256>>>(inp, W_ih, b_ih, b_hh);
    gact_tc_kernel<<<dim3(16, 64), 256, GT_SMEM_TOTAL>>>(act, W_ih);

    decoder_kernel<<<32, 256, SMEM_TOTAL>>>(W_hh, out);

    if (out_size >= L * B * H + 2 * B * H) {
        tail_kernel<<<(B * H + 255) / 256, 256>>>(out);
    }
}